// round 9
// baseline (speedup 1.0000x reference)
#include <cuda_runtime.h>
#include <cstdint>

typedef unsigned long long u64;
typedef unsigned int u32;

#define NP 131072
#define NC 128
#define TPB 128
#define NBLK (NP / TPB)   // 1024

__device__ __align__(16) float g_params[NC * 12];
__device__ float g_partial[NBLK];
__device__ u32 g_done = 0;   // self-resetting via atomicInc wrap

// ---------------------------------------------------------------------------
// Setup: 128 blocks (1/center); 6 threads do the 6 fp64 trig calls in parallel.
// Numerics identical to passing R4/R6/R7.
// layout per center (3 x float4): {cx,cy,cz,M00}{M10,M20,M01,M11}{M21,M02,M12,M22}
// ---------------------------------------------------------------------------
__global__ void setup_kernel(const float* __restrict__ centers,
                             const float* __restrict__ radii,
                             const float* __restrict__ rot) {
    __shared__ float strig[6];
    int t = threadIdx.x;
    int c = blockIdx.x;
    if (t < 6) {
        int axis = t >> 1;
        double a = (double)rot[c * 3 + axis];
        strig[t] = (t & 1) ? (float)sin(a) : (float)cos(a);
    }
    __syncthreads();
    if (t != 0) return;

    float d[3];
#pragma unroll
    for (int i = 0; i < 3; i++)
        d[i] = __fdiv_rn(1.0f, __fadd_rn(fabsf(radii[c * 3 + i]), 1e-8f));

    float cx = strig[0], sx = strig[1];
    float cy = strig[2], sy = strig[3];
    float cz = strig[4], sz = strig[5];

    float R[3][3];
    R[0][0] = __fmul_rn(cz, cy);
    R[0][1] = __fsub_rn(__fmul_rn(__fmul_rn(cz, sy), sx), __fmul_rn(sz, cx));
    R[0][2] = __fadd_rn(__fmul_rn(__fmul_rn(cz, sy), cx), __fmul_rn(sz, sx));
    R[1][0] = __fmul_rn(sz, cy);
    R[1][1] = __fadd_rn(__fmul_rn(__fmul_rn(sz, sy), sx), __fmul_rn(cz, cx));
    R[1][2] = __fsub_rn(__fmul_rn(__fmul_rn(sz, sy), cx), __fmul_rn(cz, sx));
    R[2][0] = -sy;
    R[2][1] = __fmul_rn(cy, sx);
    R[2][2] = __fmul_rn(cy, cx);

    float tmp[3][3];
#pragma unroll
    for (int a = 0; a < 3; a++)
#pragma unroll
        for (int b = 0; b < 3; b++)
            tmp[a][b] = __fmul_rn(R[a][b], d[b]);

    float M[3][3];
#pragma unroll
    for (int a = 0; a < 3; a++)
#pragma unroll
        for (int cc = 0; cc < 3; cc++)
            M[a][cc] = __fadd_rn(__fadd_rn(__fmul_rn(tmp[a][0], R[cc][0]),
                                           __fmul_rn(tmp[a][1], R[cc][1])),
                                 __fmul_rn(tmp[a][2], R[cc][2]));

    float* oA = g_params + c * 12;
    oA[0] = centers[c * 3 + 0];
    oA[1] = centers[c * 3 + 1];
    oA[2] = centers[c * 3 + 2];
    oA[3]  = M[0][0];
    oA[4]  = M[1][0]; oA[5]  = M[2][0]; oA[6]  = M[0][1]; oA[7]  = M[1][1];
    oA[8]  = M[2][1]; oA[9]  = M[0][2]; oA[10] = M[1][2]; oA[11] = M[2][2];
}

// ---------------------------------------------------------------------------
// u32 sorting network, ascending — each CE is 2x IMNMX.
// ---------------------------------------------------------------------------
__device__ __forceinline__ void ce_asc(u32& a, u32& b) {
    u32 lo = min(a, b);
    u32 hi = max(a, b);
    a = lo; b = hi;
}

__device__ __forceinline__ void sort16_asc(u32 v[16]) {
#pragma unroll
    for (int p = 1; p < 16; p <<= 1) {
#pragma unroll
        for (int k = p; k >= 1; k >>= 1) {
#pragma unroll
            for (int j = k & (p - 1); j + k < 16; j += 2 * k) {
#pragma unroll
                for (int i = 0; i < k && (i + j + k) < 16; i++) {
                    if (((i + j) / (2 * p)) == ((i + j + k) / (2 * p))) {
                        ce_asc(v[i + j], v[i + j + k]);
                    }
                }
            }
        }
    }
}

// R asc, C asc -> R = 16 smallest of union; r17 tracks min over discarded.
// CLEANUP=true re-sorts R (needed before subsequent merges).
template <bool CLEANUP>
__device__ __forceinline__ void merge16_asc(u32 R[16], const u32 C[16], u32& r17) {
    u32 hi[16];
#pragma unroll
    for (int i = 0; i < 16; i++) {
        u32 b = C[15 - i];
        hi[i] = max(R[i], b);
        R[i] = min(R[i], b);
    }
#pragma unroll
    for (int s = 8; s >= 1; s >>= 1)
#pragma unroll
        for (int i = 0; i < s; i++) hi[i] = min(hi[i], hi[i + s]);
    r17 = min(r17, hi[0]);
    if (CLEANUP) {
#pragma unroll
        for (int d = 8; d >= 1; d >>= 1) {
#pragma unroll
            for (int i = 0; i < 16; i++) {
                if ((i & d) == 0) ce_asc(R[i], R[i + d]);
            }
        }
    }
}

__device__ __forceinline__ float ex2_fast(float x) {
    float r;
    asm("ex2.approx.f32 %0, %1;" : "=f"(r) : "f"(x));
    return r;
}

// Quadratic form — bit-identical grouping to the passing R4/R6/R7 kernels.
__device__ __forceinline__ float quadA(const float4* sA, int c,
                                       float x, float y, float z) {
    float4 a0 = sA[c * 3 + 0];
    float4 a1 = sA[c * 3 + 1];
    float4 a2 = sA[c * 3 + 2];
    float dx = x - a0.x, dy = y - a0.y, dz = z - a0.z;
    float t0 = fmaf(dz, a1.y, fmaf(dy, a1.x, __fmul_rn(dx, a0.w)));
    float t1 = fmaf(dz, a2.x, fmaf(dy, a1.w, __fmul_rn(dx, a1.z)));
    float t2 = fmaf(dz, a2.w, fmaf(dy, a2.z, __fmul_rn(dx, a2.y)));
    return __fadd_rn(__fadd_rn(__fmul_rn(t0, dx), __fmul_rn(t1, dy)),
                     __fmul_rn(t2, dz));
}

// ---------------------------------------------------------------------------
// Main: one thread per point. Scalar math only (f32x2 proven slow on sm_103a).
// Keys = (qbits & ~0x7F) | idx; exact-set proof via r17 boundary check;
// rare exact fallback. Integrated last-block finalize.
// ---------------------------------------------------------------------------
__global__ void __launch_bounds__(TPB, 5)
main_kernel(const float* __restrict__ xyz,
            const float4* __restrict__ rgbs,
            const float* __restrict__ dists,
            const float* __restrict__ centers,
            float* __restrict__ out, int out_size) {
    __shared__ float4 sA[NC * 3];   // 6 KB
    __shared__ float sred[TPB];
    __shared__ bool sLast;

    int tid = threadIdx.x;
#pragma unroll
    for (int i = tid; i < NC * 3; i += TPB)
        sA[i] = reinterpret_cast<const float4*>(g_params)[i];
    __syncthreads();

    int p = blockIdx.x * TPB + tid;
    float x = xyz[3 * p + 0];
    float y = xyz[3 * p + 1];
    float z = xyz[3 * p + 2];

    u32 R[16];
    u32 r17 = 0xFFFFFFFFu;
    float pen = 0.0f;
    const float CEXP = -0.72134752044448170f;  // -0.5*log2(e)
    const float K_ADD = 2.3219280948873623f;   // log2(5)

    // ---- Pass 1: scalar q for all centers; sort (truncq|idx) keys ----
#pragma unroll 1
    for (int base = 0; base < 8; base++) {
        u32 C[16];
#pragma unroll
        for (int j = 0; j < 16; j++) {
            int c = base * 16 + j;
            float q = quadA(sA, c, x, y, z);
            float e = ex2_fast(fmaf(q, CEXP, K_ADD));
            pen += fmaxf(e - 0.01f, 0.0f);
            u32 qb = __float_as_uint(fmaxf(q, 0.0f));
            C[j] = (qb & 0xFFFFFF80u) | (u32)c;
        }
        sort16_asc(C);
        if (base == 0) {
#pragma unroll
            for (int i = 0; i < 16; i++) R[i] = C[i];
        } else if (base < 7) {
            merge16_asc<true>(R, C, r17);
        } else {
            merge16_asc<false>(R, C, r17);  // final: set only, no cleanup
        }
    }

    // boundary key (16th by (q,idx)) via max-tree
    u32 tq = R[0];
#pragma unroll
    for (int i = 1; i < 16; i++) tq = max(tq, R[i]);

    // ---- Rare exact fallback: truncated 16/17 boundary tie ----
    if (((tq ^ r17) & 0xFFFFFF80u) == 0u) {
        u64 prev = 0ull;
#pragma unroll 1
        for (int r = 0; r < 16; r++) {
            u64 best = ~0ull;
#pragma unroll 1
            for (int c = 0; c < NC; c++) {
                float q = quadA(sA, c, x, y, z);
                u32 qb = __float_as_uint(fmaxf(q, 0.0f));
                u64 k = (((u64)qb << 7) | (u32)c) + 1ull;
                if (k > prev && k < best) best = k;
            }
            prev = best;
            R[r] = (u32)((best - 1ull) & 0x7Full);
        }
    }

    // ---- Gather: 16 selected; exact weight from recomputed scalar q ----
    float dp = dists[p];
    const float LOG2E = 1.4426950408889634f;
    float sumw = 0.0f;
    float o0 = 0.0f, o1 = 0.0f, o2 = 0.0f, o3 = 0.0f;
#pragma unroll
    for (int i = 0; i < 16; i++) {
        int c = (int)(R[i] & 0x7Fu);
        float q = quadA(sA, c, x, y, z);
        float qc = fmaxf(q, 0.0f);
        float w = __fmul_rn(5.0f, ex2_fast(__fmul_rn(qc, CEXP)));
        w = (w >= 0.01f) ? w : 0.0f;
        sumw += w;
        if (w > 0.0f) {
            float4 g = __ldg(&rgbs[(size_t)c * NP + p]);
            float alpha = 1.0f - ex2_fast(fmaxf(g.w, 0.0f) * dp * (-LOG2E));
            o0 = fmaf(w, g.x, o0);
            o1 = fmaf(w, g.y, o1);
            o2 = fmaf(w, g.z, o2);
            o3 = fmaf(w, alpha, o3);
        }
    }
    float inv = __fdiv_rn(1.0f, __fadd_rn(sumw, 1e-7f));
    reinterpret_cast<float4*>(out)[p] =
        make_float4(o0 * inv, o1 * inv, o2 * inv, o3 * inv);

    // ---- deterministic block reduction of penalty ----
    sred[tid] = pen;
    __syncthreads();
#pragma unroll
    for (int s = TPB / 2; s > 0; s >>= 1) {
        if (tid < s) sred[tid] += sred[tid + s];
        __syncthreads();
    }
    if (tid == 0) {
        g_partial[blockIdx.x] = sred[0];
        __threadfence();
        u32 old = atomicInc(&g_done, NBLK - 1);
        sLast = (old == NBLK - 1);
    }
    __syncthreads();

    // ---- Last block: finalize pen (deterministic fixed-order sum) ----
    if (sLast) {
        __shared__ double sd[TPB];
        double s = 0.0;
#pragma unroll
        for (int i = 0; i < NBLK / TPB; i++)
            s += (double)g_partial[tid * (NBLK / TPB) + i];
        sd[tid] = s;
        __syncthreads();
        if (tid == 0) {
            double tot = 0.0;
            for (int i = 0; i < TPB; i++) tot += sd[i];
            float bbox = 0.0f;
            for (int i = 0; i < NC * 3; i++) {
                float v = centers[i];
                bbox += fmaxf(v - 0.5f, 0.0f) + fmaxf(-0.5f - v, 0.0f);
            }
            float pv = (float)(0.001 * tot / (double)NP) + bbox;
            if (out_size > 4 * NP) {
                out[4 * NP] = pv;
                out[out_size - 1] = pv;
            }
        }
    }
}

// ---------------------------------------------------------------------------
extern "C" void kernel_launch(void* const* d_in, const int* in_sizes, int n_in,
                              void* d_out, int out_size) {
    const float* xyz = nullptr;
    const float* dists = nullptr;
    const float4* rgbs = nullptr;
    const float* small3[3] = {nullptr, nullptr, nullptr};
    int nsmall = 0;
    for (int i = 0; i < n_in; i++) {
        int sz = in_sizes[i];
        if (sz == NP * 3)                xyz   = (const float*)d_in[i];
        else if (sz == NC * NP * 4)      rgbs  = (const float4*)d_in[i];
        else if (sz == NP)               dists = (const float*)d_in[i];
        else if (sz == NC * 3 && nsmall < 3) small3[nsmall++] = (const float*)d_in[i];
    }
    const float* centers = small3[0];
    const float* radii   = small3[1];
    const float* rots    = small3[2];

    setup_kernel<<<NC, 8>>>(centers, radii, rots);
    main_kernel<<<NBLK, TPB>>>(xyz, rgbs, dists, centers, (float*)d_out, out_size);
}

// round 10
// speedup vs baseline: 1.0038x; 1.0038x over previous
#include <cuda_runtime.h>
#include <cstdint>

typedef unsigned long long u64;
typedef unsigned int u32;

#define NP 131072
#define NC 128
#define TPB 128
#define NBLK (NP / TPB)   // 1024

__device__ __align__(16) float g_params[NC * 12];
__device__ float g_partial[NBLK];
__device__ u32 g_done = 0;   // self-resetting via atomicInc wrap

// ---------------------------------------------------------------------------
// Setup: 128 blocks (1/center); 6 threads do the 6 fp64 trig calls in parallel.
// Numerics identical to passing R4/R6/R7.
// layout per center (3 x float4): {cx,cy,cz,M00}{M10,M20,M01,M11}{M21,M02,M12,M22}
// ---------------------------------------------------------------------------
__global__ void setup_kernel(const float* __restrict__ centers,
                             const float* __restrict__ radii,
                             const float* __restrict__ rot) {
    __shared__ float strig[6];
    int t = threadIdx.x;
    int c = blockIdx.x;
    if (t < 6) {
        int axis = t >> 1;
        double a = (double)rot[c * 3 + axis];
        strig[t] = (t & 1) ? (float)sin(a) : (float)cos(a);
    }
    __syncthreads();
    if (t != 0) return;

    float d[3];
#pragma unroll
    for (int i = 0; i < 3; i++)
        d[i] = __fdiv_rn(1.0f, __fadd_rn(fabsf(radii[c * 3 + i]), 1e-8f));

    float cx = strig[0], sx = strig[1];
    float cy = strig[2], sy = strig[3];
    float cz = strig[4], sz = strig[5];

    float R[3][3];
    R[0][0] = __fmul_rn(cz, cy);
    R[0][1] = __fsub_rn(__fmul_rn(__fmul_rn(cz, sy), sx), __fmul_rn(sz, cx));
    R[0][2] = __fadd_rn(__fmul_rn(__fmul_rn(cz, sy), cx), __fmul_rn(sz, sx));
    R[1][0] = __fmul_rn(sz, cy);
    R[1][1] = __fadd_rn(__fmul_rn(__fmul_rn(sz, sy), sx), __fmul_rn(cz, cx));
    R[1][2] = __fsub_rn(__fmul_rn(__fmul_rn(sz, sy), cx), __fmul_rn(cz, sx));
    R[2][0] = -sy;
    R[2][1] = __fmul_rn(cy, sx);
    R[2][2] = __fmul_rn(cy, cx);

    float tmp[3][3];
#pragma unroll
    for (int a = 0; a < 3; a++)
#pragma unroll
        for (int b = 0; b < 3; b++)
            tmp[a][b] = __fmul_rn(R[a][b], d[b]);

    float M[3][3];
#pragma unroll
    for (int a = 0; a < 3; a++)
#pragma unroll
        for (int cc = 0; cc < 3; cc++)
            M[a][cc] = __fadd_rn(__fadd_rn(__fmul_rn(tmp[a][0], R[cc][0]),
                                           __fmul_rn(tmp[a][1], R[cc][1])),
                                 __fmul_rn(tmp[a][2], R[cc][2]));

    float* oA = g_params + c * 12;
    oA[0] = centers[c * 3 + 0];
    oA[1] = centers[c * 3 + 1];
    oA[2] = centers[c * 3 + 2];
    oA[3]  = M[0][0];
    oA[4]  = M[1][0]; oA[5]  = M[2][0]; oA[6]  = M[0][1]; oA[7]  = M[1][1];
    oA[8]  = M[2][1]; oA[9]  = M[0][2]; oA[10] = M[1][2]; oA[11] = M[2][2];
}

// ---------------------------------------------------------------------------
// u32 sorting network, ascending — each CE is 2x IMNMX. All static indexing.
// ---------------------------------------------------------------------------
__device__ __forceinline__ void ce_asc(u32& a, u32& b) {
    u32 lo = min(a, b);
    u32 hi = max(a, b);
    a = lo; b = hi;
}

__device__ __forceinline__ void sort16_asc(u32 v[16]) {
#pragma unroll
    for (int p = 1; p < 16; p <<= 1) {
#pragma unroll
        for (int k = p; k >= 1; k >>= 1) {
#pragma unroll
            for (int j = k & (p - 1); j + k < 16; j += 2 * k) {
#pragma unroll
                for (int i = 0; i < k && (i + j + k) < 16; i++) {
                    if (((i + j) / (2 * p)) == ((i + j + k) / (2 * p))) {
                        ce_asc(v[i + j], v[i + j + k]);
                    }
                }
            }
        }
    }
}

// R asc, C asc -> R = 16 smallest of union; r17 tracks min over discarded.
// CLEANUP=true re-sorts R (needed before subsequent merges).
template <bool CLEANUP>
__device__ __forceinline__ void merge16_asc(u32 R[16], const u32 C[16], u32& r17) {
    u32 hi[16];
#pragma unroll
    for (int i = 0; i < 16; i++) {
        u32 b = C[15 - i];
        hi[i] = max(R[i], b);
        R[i] = min(R[i], b);
    }
#pragma unroll
    for (int s = 8; s >= 1; s >>= 1)
#pragma unroll
        for (int i = 0; i < s; i++) hi[i] = min(hi[i], hi[i + s]);
    r17 = min(r17, hi[0]);
    if (CLEANUP) {
#pragma unroll
        for (int d = 8; d >= 1; d >>= 1) {
#pragma unroll
            for (int i = 0; i < 16; i++) {
                if ((i & d) == 0) ce_asc(R[i], R[i + d]);
            }
        }
    }
}

__device__ __forceinline__ float ex2_fast(float x) {
    float r;
    asm("ex2.approx.f32 %0, %1;" : "=f"(r) : "f"(x));
    return r;
}

// Quadratic form — bit-identical grouping to the passing R4/R6/R7 kernels.
__device__ __forceinline__ float quadA(const float4* sA, int c,
                                       float x, float y, float z) {
    float4 a0 = sA[c * 3 + 0];
    float4 a1 = sA[c * 3 + 1];
    float4 a2 = sA[c * 3 + 2];
    float dx = x - a0.x, dy = y - a0.y, dz = z - a0.z;
    float t0 = fmaf(dz, a1.y, fmaf(dy, a1.x, __fmul_rn(dx, a0.w)));
    float t1 = fmaf(dz, a2.x, fmaf(dy, a1.w, __fmul_rn(dx, a1.z)));
    float t2 = fmaf(dz, a2.w, fmaf(dy, a2.z, __fmul_rn(dx, a2.y)));
    return __fadd_rn(__fadd_rn(__fmul_rn(t0, dx), __fmul_rn(t1, dy)),
                     __fmul_rn(t2, dz));
}

// ---------------------------------------------------------------------------
// Main: one thread per point. Keys = (qbits & ~0x7F) | idx; exact-set proof
// via r17 boundary check; rare fallback writes SMEM (never dynamic reg index).
// ---------------------------------------------------------------------------
__global__ void __launch_bounds__(TPB, 5)
main_kernel(const float* __restrict__ xyz,
            const float4* __restrict__ rgbs,
            const float* __restrict__ dists,
            const float* __restrict__ centers,
            float* __restrict__ out, int out_size) {
    __shared__ float4 sA[NC * 3];             // 6 KB
    __shared__ unsigned char slist[TPB * 16]; // 2 KB: selected indices
    __shared__ float sred[TPB];
    __shared__ bool sLast;

    int tid = threadIdx.x;
#pragma unroll
    for (int i = tid; i < NC * 3; i += TPB)
        sA[i] = reinterpret_cast<const float4*>(g_params)[i];
    __syncthreads();

    int p = blockIdx.x * TPB + tid;
    float x = xyz[3 * p + 0];
    float y = xyz[3 * p + 1];
    float z = xyz[3 * p + 2];

    u32 R[16];
    u32 r17 = 0xFFFFFFFFu;
    float pen = 0.0f;
    const float CEXP = -0.72134752044448170f;  // -0.5*log2(e)
    const float K_ADD = 2.3219280948873623f;   // log2(5)

    // ---- Pass 1: scalar q for all centers; sort (truncq|idx) keys ----
#pragma unroll 1
    for (int base = 0; base < 8; base++) {
        u32 C[16];
#pragma unroll
        for (int j = 0; j < 16; j++) {
            int c = base * 16 + j;
            float q = quadA(sA, c, x, y, z);
            float e = ex2_fast(fmaf(q, CEXP, K_ADD));
            pen += fmaxf(e - 0.01f, 0.0f);
            u32 qb = __float_as_uint(fmaxf(q, 0.0f));
            C[j] = (qb & 0xFFFFFF80u) | (u32)c;
        }
        sort16_asc(C);
        if (base == 0) {
#pragma unroll
            for (int i = 0; i < 16; i++) R[i] = C[i];
        } else if (base < 7) {
            merge16_asc<true>(R, C, r17);
        } else {
            merge16_asc<false>(R, C, r17);  // final: set only, no cleanup
        }
    }

    // boundary key (16th by (q,idx)) via max-tree
    u32 tq = R[0];
#pragma unroll
    for (int i = 1; i < 16; i++) tq = max(tq, R[i]);

    // Common path: static unrolled writes of selected indices to smem.
    unsigned char* mylist = slist + tid * 16;
#pragma unroll
    for (int i = 0; i < 16; i++) mylist[i] = (unsigned char)(R[i] & 0x7Fu);

    // ---- Rare exact fallback (truncated 16/17 boundary tie).
    //      Writes go to SMEM (dynamic smem indexing is fine; keeps R in regs).
    if (((tq ^ r17) & 0xFFFFFF80u) == 0u) {
        u64 prev = 0ull;
#pragma unroll 1
        for (int r = 0; r < 16; r++) {
            u64 best = ~0ull;
#pragma unroll 1
            for (int c = 0; c < NC; c++) {
                float q = quadA(sA, c, x, y, z);
                u32 qb = __float_as_uint(fmaxf(q, 0.0f));
                u64 k = (((u64)qb << 7) | (u32)c) + 1ull;
                if (k > prev && k < best) best = k;
            }
            prev = best;
            mylist[r] = (unsigned char)((best - 1ull) & 0x7Full);
        }
    }

    // ---- Gather: 16 selected; exact weight from recomputed scalar q ----
    float dp = dists[p];
    const float LOG2E = 1.4426950408889634f;
    float sumw = 0.0f;
    float o0 = 0.0f, o1 = 0.0f, o2 = 0.0f, o3 = 0.0f;
#pragma unroll
    for (int i = 0; i < 16; i++) {
        int c = (int)mylist[i];
        float q = quadA(sA, c, x, y, z);
        float qc = fmaxf(q, 0.0f);
        float w = __fmul_rn(5.0f, ex2_fast(__fmul_rn(qc, CEXP)));
        w = (w >= 0.01f) ? w : 0.0f;
        sumw += w;
        if (w > 0.0f) {
            float4 g = __ldg(&rgbs[(size_t)c * NP + p]);
            float alpha = 1.0f - ex2_fast(fmaxf(g.w, 0.0f) * dp * (-LOG2E));
            o0 = fmaf(w, g.x, o0);
            o1 = fmaf(w, g.y, o1);
            o2 = fmaf(w, g.z, o2);
            o3 = fmaf(w, alpha, o3);
        }
    }
    float inv = __fdiv_rn(1.0f, __fadd_rn(sumw, 1e-7f));
    reinterpret_cast<float4*>(out)[p] =
        make_float4(o0 * inv, o1 * inv, o2 * inv, o3 * inv);

    // ---- deterministic block reduction of penalty ----
    sred[tid] = pen;
    __syncthreads();
#pragma unroll
    for (int s = TPB / 2; s > 0; s >>= 1) {
        if (tid < s) sred[tid] += sred[tid + s];
        __syncthreads();
    }
    if (tid == 0) {
        g_partial[blockIdx.x] = sred[0];
        __threadfence();
        u32 old = atomicInc(&g_done, NBLK - 1);
        sLast = (old == NBLK - 1);
    }
    __syncthreads();

    // ---- Last block: finalize pen (deterministic fixed-order sum) ----
    if (sLast) {
        __shared__ double sd[TPB];
        double s = 0.0;
#pragma unroll
        for (int i = 0; i < NBLK / TPB; i++)
            s += (double)g_partial[tid * (NBLK / TPB) + i];
        sd[tid] = s;
        __syncthreads();
        if (tid == 0) {
            double tot = 0.0;
            for (int i = 0; i < TPB; i++) tot += sd[i];
            float bbox = 0.0f;
            for (int i = 0; i < NC * 3; i++) {
                float v = centers[i];
                bbox += fmaxf(v - 0.5f, 0.0f) + fmaxf(-0.5f - v, 0.0f);
            }
            float pv = (float)(0.001 * tot / (double)NP) + bbox;
            if (out_size > 4 * NP) {
                out[4 * NP] = pv;
                out[out_size - 1] = pv;
            }
        }
    }
}

// ---------------------------------------------------------------------------
extern "C" void kernel_launch(void* const* d_in, const int* in_sizes, int n_in,
                              void* d_out, int out_size) {
    const float* xyz = nullptr;
    const float* dists = nullptr;
    const float4* rgbs = nullptr;
    const float* small3[3] = {nullptr, nullptr, nullptr};
    int nsmall = 0;
    for (int i = 0; i < n_in; i++) {
        int sz = in_sizes[i];
        if (sz == NP * 3)                xyz   = (const float*)d_in[i];
        else if (sz == NC * NP * 4)      rgbs  = (const float4*)d_in[i];
        else if (sz == NP)               dists = (const float*)d_in[i];
        else if (sz == NC * 3 && nsmall < 3) small3[nsmall++] = (const float*)d_in[i];
    }
    const float* centers = small3[0];
    const float* radii   = small3[1];
    const float* rots    = small3[2];

    setup_kernel<<<NC, 8>>>(centers, radii, rots);
    main_kernel<<<NBLK, TPB>>>(xyz, rgbs, dists, centers, (float*)d_out, out_size);
}

// round 11
// speedup vs baseline: 2.3579x; 2.3490x over previous
#include <cuda_runtime.h>
#include <cstdint>

typedef unsigned long long u64;
typedef unsigned int u32;

#define NP 131072
#define NC 128
#define TPB 128
#define NBLK (NP / TPB)   // 1024

__device__ __align__(16) float g_params[NC * 12];
__device__ float g_partial[NBLK];
__device__ u32 g_done = 0;   // self-resetting via atomicInc wrap

// ---------------------------------------------------------------------------
// Setup: 128 blocks (1/center); 6 threads do the 6 fp64 trig calls in parallel.
// Numerics identical to passing R4/R6/R7.
// ---------------------------------------------------------------------------
__global__ void setup_kernel(const float* __restrict__ centers,
                             const float* __restrict__ radii,
                             const float* __restrict__ rot) {
    __shared__ float strig[6];
    int t = threadIdx.x;
    int c = blockIdx.x;
    if (t < 6) {
        int axis = t >> 1;
        double a = (double)rot[c * 3 + axis];
        strig[t] = (t & 1) ? (float)sin(a) : (float)cos(a);
    }
    __syncthreads();
    if (t != 0) return;

    float d[3];
#pragma unroll
    for (int i = 0; i < 3; i++)
        d[i] = __fdiv_rn(1.0f, __fadd_rn(fabsf(radii[c * 3 + i]), 1e-8f));

    float cx = strig[0], sx = strig[1];
    float cy = strig[2], sy = strig[3];
    float cz = strig[4], sz = strig[5];

    float R[3][3];
    R[0][0] = __fmul_rn(cz, cy);
    R[0][1] = __fsub_rn(__fmul_rn(__fmul_rn(cz, sy), sx), __fmul_rn(sz, cx));
    R[0][2] = __fadd_rn(__fmul_rn(__fmul_rn(cz, sy), cx), __fmul_rn(sz, sx));
    R[1][0] = __fmul_rn(sz, cy);
    R[1][1] = __fadd_rn(__fmul_rn(__fmul_rn(sz, sy), sx), __fmul_rn(cz, cx));
    R[1][2] = __fsub_rn(__fmul_rn(__fmul_rn(sz, sy), cx), __fmul_rn(cz, sx));
    R[2][0] = -sy;
    R[2][1] = __fmul_rn(cy, sx);
    R[2][2] = __fmul_rn(cy, cx);

    float tmp[3][3];
#pragma unroll
    for (int a = 0; a < 3; a++)
#pragma unroll
        for (int b = 0; b < 3; b++)
            tmp[a][b] = __fmul_rn(R[a][b], d[b]);

    float M[3][3];
#pragma unroll
    for (int a = 0; a < 3; a++)
#pragma unroll
        for (int cc = 0; cc < 3; cc++)
            M[a][cc] = __fadd_rn(__fadd_rn(__fmul_rn(tmp[a][0], R[cc][0]),
                                           __fmul_rn(tmp[a][1], R[cc][1])),
                                 __fmul_rn(tmp[a][2], R[cc][2]));

    float* oA = g_params + c * 12;
    oA[0] = centers[c * 3 + 0];
    oA[1] = centers[c * 3 + 1];
    oA[2] = centers[c * 3 + 2];
    oA[3]  = M[0][0];
    oA[4]  = M[1][0]; oA[5]  = M[2][0]; oA[6]  = M[0][1]; oA[7]  = M[1][1];
    oA[8]  = M[2][1]; oA[9]  = M[0][2]; oA[10] = M[1][2]; oA[11] = M[2][2];
}

// ---------------------------------------------------------------------------
// u32 sorting network, ascending — each CE is 2x IMNMX. All static indexing.
// ---------------------------------------------------------------------------
__device__ __forceinline__ void ce_asc(u32& a, u32& b) {
    u32 lo = min(a, b);
    u32 hi = max(a, b);
    a = lo; b = hi;
}

__device__ __forceinline__ void sort16_asc(u32 v[16]) {
#pragma unroll
    for (int p = 1; p < 16; p <<= 1) {
#pragma unroll
        for (int k = p; k >= 1; k >>= 1) {
#pragma unroll
            for (int j = k & (p - 1); j + k < 16; j += 2 * k) {
#pragma unroll
                for (int i = 0; i < k && (i + j + k) < 16; i++) {
                    if (((i + j) / (2 * p)) == ((i + j + k) / (2 * p))) {
                        ce_asc(v[i + j], v[i + j + k]);
                    }
                }
            }
        }
    }
}

// R asc, C asc -> R = 16 smallest of union; r17 = min over discarded (scalar).
template <bool CLEANUP>
__device__ __forceinline__ void merge16_asc(u32 R[16], const u32 C[16], u32& r17) {
#pragma unroll
    for (int i = 0; i < 16; i++) {
        u32 b = C[15 - i];
        u32 mx = max(R[i], b);
        R[i] = min(R[i], b);
        r17 = min(r17, mx);
    }
    if (CLEANUP) {
#pragma unroll
        for (int d = 8; d >= 1; d >>= 1) {
#pragma unroll
            for (int i = 0; i < 16; i++) {
                if ((i & d) == 0) ce_asc(R[i], R[i + d]);
            }
        }
    }
}

__device__ __forceinline__ float ex2_fast(float x) {
    float r;
    asm("ex2.approx.f32 %0, %1;" : "=f"(r) : "f"(x));
    return r;
}

// Quadratic form — bit-identical grouping to the passing R4/R6/R7 kernels.
__device__ __forceinline__ float quadA(const float4* sA, int c,
                                       float x, float y, float z) {
    float4 a0 = sA[c * 3 + 0];
    float4 a1 = sA[c * 3 + 1];
    float4 a2 = sA[c * 3 + 2];
    float dx = x - a0.x, dy = y - a0.y, dz = z - a0.z;
    float t0 = fmaf(dz, a1.y, fmaf(dy, a1.x, __fmul_rn(dx, a0.w)));
    float t1 = fmaf(dz, a2.x, fmaf(dy, a1.w, __fmul_rn(dx, a1.z)));
    float t2 = fmaf(dz, a2.w, fmaf(dy, a2.z, __fmul_rn(dx, a2.y)));
    return __fadd_rn(__fadd_rn(__fmul_rn(t0, dx), __fmul_rn(t1, dy)),
                     __fmul_rn(t2, dz));
}

// ---------------------------------------------------------------------------
// Main: one thread per point. Keys = (qbits & ~0x7F) | idx. On a truncated
// 16/17 boundary tie: ONE exact rescan + tiny in-bucket selection (cheap),
// not a full re-selection. Integrated last-block finalize.
// ---------------------------------------------------------------------------
__global__ void __launch_bounds__(TPB, 5)
main_kernel(const float* __restrict__ xyz,
            const float4* __restrict__ rgbs,
            const float* __restrict__ dists,
            const float* __restrict__ centers,
            float* __restrict__ out, int out_size) {
    __shared__ float4 sA[NC * 3];             // 6 KB
    __shared__ unsigned char slist[TPB * 16]; // 2 KB: selected indices
    __shared__ u64 sbucket[TPB * 8];          // 8 KB: boundary-bucket scratch
    __shared__ float sred[TPB];
    __shared__ bool sLast;

    int tid = threadIdx.x;
#pragma unroll
    for (int i = tid; i < NC * 3; i += TPB)
        sA[i] = reinterpret_cast<const float4*>(g_params)[i];
    __syncthreads();

    int p = blockIdx.x * TPB + tid;
    float x = xyz[3 * p + 0];
    float y = xyz[3 * p + 1];
    float z = xyz[3 * p + 2];

    u32 R[16];
    u32 r17 = 0xFFFFFFFFu;
    float pen = 0.0f;
    const float CEXP = -0.72134752044448170f;  // -0.5*log2(e)
    const float K_ADD = 2.3219280948873623f;   // log2(5)

    // ---- Pass 1: scalar q for all centers; sort (truncq|idx) keys ----
#pragma unroll 1
    for (int base = 0; base < 8; base++) {
        u32 C[16];
#pragma unroll
        for (int j = 0; j < 16; j++) {
            int c = base * 16 + j;
            float q = quadA(sA, c, x, y, z);
            float e = ex2_fast(fmaf(q, CEXP, K_ADD));
            pen += fmaxf(e - 0.01f, 0.0f);
            u32 qb = __float_as_uint(fmaxf(q, 0.0f));
            C[j] = (qb & 0xFFFFFF80u) | (u32)c;
        }
        sort16_asc(C);
        if (base == 0) {
#pragma unroll
            for (int i = 0; i < 16; i++) R[i] = C[i];
        } else if (base < 7) {
            merge16_asc<true>(R, C, r17);
        } else {
            merge16_asc<false>(R, C, r17);  // final: set only, no cleanup
        }
    }

    // boundary key (16th by (truncq,idx)) via max-tree
    u32 tq = R[0];
#pragma unroll
    for (int i = 1; i < 16; i++) tq = max(tq, R[i]);

    // Common path: selected indices straight from keys (static unroll).
    unsigned char* ml = slist + tid * 16;
#pragma unroll
    for (int i = 0; i < 16; i++) ml[i] = (unsigned char)(R[i] & 0x7Fu);

    // ---- Boundary-tie resolution: one exact rescan + in-bucket pick ----
    if (((tq ^ r17) & 0xFFFFFF80u) == 0u) {
        u32 btr = tq & 0xFFFFFF80u;
        u64* myb = sbucket + tid * 8;
        int m = 0, nb = 0;
#pragma unroll 1
        for (int c = 0; c < NC; c++) {
            float q = quadA(sA, c, x, y, z);
            u32 qb = __float_as_uint(fmaxf(q, 0.0f));
            u32 t = qb & 0xFFFFFF80u;
            if (t < btr) {               // provably in top-16
                ml[m] = (unsigned char)c;
                m++;
            } else if (t == btr && nb < 8) {
                myb[nb] = (((u64)qb << 7) | (u32)c) + 1ull;
                nb++;
            }
        }
        // pick the (16-m) smallest bucket members by exact (q, idx)
        u64 prev = 0ull;
#pragma unroll 1
        for (int r = m; r < 16; r++) {
            u64 best = ~0ull;
#pragma unroll 1
            for (int i = 0; i < nb; i++) {
                u64 k = myb[i];
                if (k > prev && k < best) best = k;
            }
            prev = best;
            ml[r] = (unsigned char)((best - 1ull) & 0x7Fu);
        }
    }

    // ---- Gather: 16 selected; exact weight from recomputed scalar q ----
    float dp = dists[p];
    const float LOG2E = 1.4426950408889634f;
    float sumw = 0.0f;
    float o0 = 0.0f, o1 = 0.0f, o2 = 0.0f, o3 = 0.0f;
#pragma unroll
    for (int i = 0; i < 16; i++) {
        int c = (int)ml[i];
        float q = quadA(sA, c, x, y, z);
        float qc = fmaxf(q, 0.0f);
        float w = __fmul_rn(5.0f, ex2_fast(__fmul_rn(qc, CEXP)));
        w = (w >= 0.01f) ? w : 0.0f;
        sumw += w;
        if (w > 0.0f) {
            float4 g = __ldg(&rgbs[(size_t)c * NP + p]);
            float alpha = 1.0f - ex2_fast(fmaxf(g.w, 0.0f) * dp * (-LOG2E));
            o0 = fmaf(w, g.x, o0);
            o1 = fmaf(w, g.y, o1);
            o2 = fmaf(w, g.z, o2);
            o3 = fmaf(w, alpha, o3);
        }
    }
    float inv = __fdiv_rn(1.0f, __fadd_rn(sumw, 1e-7f));
    reinterpret_cast<float4*>(out)[p] =
        make_float4(o0 * inv, o1 * inv, o2 * inv, o3 * inv);

    // ---- deterministic block reduction of penalty ----
    sred[tid] = pen;
    __syncthreads();
#pragma unroll
    for (int s = TPB / 2; s > 0; s >>= 1) {
        if (tid < s) sred[tid] += sred[tid + s];
        __syncthreads();
    }
    if (tid == 0) {
        g_partial[blockIdx.x] = sred[0];
        __threadfence();
        u32 old = atomicInc(&g_done, NBLK - 1);
        sLast = (old == NBLK - 1);
    }
    __syncthreads();

    // ---- Last block: finalize pen (deterministic fixed-order sum) ----
    if (sLast) {
        __shared__ double sd[TPB];
        double s = 0.0;
#pragma unroll
        for (int i = 0; i < NBLK / TPB; i++)
            s += (double)g_partial[tid * (NBLK / TPB) + i];
        sd[tid] = s;
        __syncthreads();
        if (tid == 0) {
            double tot = 0.0;
            for (int i = 0; i < TPB; i++) tot += sd[i];
            float bbox = 0.0f;
            for (int i = 0; i < NC * 3; i++) {
                float v = centers[i];
                bbox += fmaxf(v - 0.5f, 0.0f) + fmaxf(-0.5f - v, 0.0f);
            }
            float pv = (float)(0.001 * tot / (double)NP) + bbox;
            if (out_size > 4 * NP) {
                out[4 * NP] = pv;
                out[out_size - 1] = pv;
            }
        }
    }
}

// ---------------------------------------------------------------------------
extern "C" void kernel_launch(void* const* d_in, const int* in_sizes, int n_in,
                              void* d_out, int out_size) {
    const float* xyz = nullptr;
    const float* dists = nullptr;
    const float4* rgbs = nullptr;
    const float* small3[3] = {nullptr, nullptr, nullptr};
    int nsmall = 0;
    for (int i = 0; i < n_in; i++) {
        int sz = in_sizes[i];
        if (sz == NP * 3)                xyz   = (const float*)d_in[i];
        else if (sz == NC * NP * 4)      rgbs  = (const float4*)d_in[i];
        else if (sz == NP)               dists = (const float*)d_in[i];
        else if (sz == NC * 3 && nsmall < 3) small3[nsmall++] = (const float*)d_in[i];
    }
    const float* centers = small3[0];
    const float* radii   = small3[1];
    const float* rots    = small3[2];

    setup_kernel<<<NC, 8>>>(centers, radii, rots);
    main_kernel<<<NBLK, TPB>>>(xyz, rgbs, dists, centers, (float*)d_out, out_size);
}

// round 12
// speedup vs baseline: 2.3663x; 1.0036x over previous
#include <cuda_runtime.h>
#include <cstdint>

typedef unsigned long long u64;
typedef unsigned int u32;

#define NP 131072
#define NC 128
#define TPB 128
#define NBLK (NP / TPB)   // 1024

__device__ __align__(16) float g_params[NC * 12];
__device__ float g_partial[NBLK];
__device__ u32 g_done = 0;   // self-resetting via atomicInc wrap

// ---------------------------------------------------------------------------
// Setup: 128 blocks (1/center); 6 threads do the 6 fp64 trig calls in parallel.
// Numerics identical to passing R4/R6/R7/R11.
// ---------------------------------------------------------------------------
__global__ void setup_kernel(const float* __restrict__ centers,
                             const float* __restrict__ radii,
                             const float* __restrict__ rot) {
    __shared__ float strig[6];
    int t = threadIdx.x;
    int c = blockIdx.x;
    if (t < 6) {
        int axis = t >> 1;
        double a = (double)rot[c * 3 + axis];
        strig[t] = (t & 1) ? (float)sin(a) : (float)cos(a);
    }
    __syncthreads();
    if (t != 0) return;

    float d[3];
#pragma unroll
    for (int i = 0; i < 3; i++)
        d[i] = __fdiv_rn(1.0f, __fadd_rn(fabsf(radii[c * 3 + i]), 1e-8f));

    float cx = strig[0], sx = strig[1];
    float cy = strig[2], sy = strig[3];
    float cz = strig[4], sz = strig[5];

    float R[3][3];
    R[0][0] = __fmul_rn(cz, cy);
    R[0][1] = __fsub_rn(__fmul_rn(__fmul_rn(cz, sy), sx), __fmul_rn(sz, cx));
    R[0][2] = __fadd_rn(__fmul_rn(__fmul_rn(cz, sy), cx), __fmul_rn(sz, sx));
    R[1][0] = __fmul_rn(sz, cy);
    R[1][1] = __fadd_rn(__fmul_rn(__fmul_rn(sz, sy), sx), __fmul_rn(cz, cx));
    R[1][2] = __fsub_rn(__fmul_rn(__fmul_rn(sz, sy), cx), __fmul_rn(cz, sx));
    R[2][0] = -sy;
    R[2][1] = __fmul_rn(cy, sx);
    R[2][2] = __fmul_rn(cy, cx);

    float tmp[3][3];
#pragma unroll
    for (int a = 0; a < 3; a++)
#pragma unroll
        for (int b = 0; b < 3; b++)
            tmp[a][b] = __fmul_rn(R[a][b], d[b]);

    float M[3][3];
#pragma unroll
    for (int a = 0; a < 3; a++)
#pragma unroll
        for (int cc = 0; cc < 3; cc++)
            M[a][cc] = __fadd_rn(__fadd_rn(__fmul_rn(tmp[a][0], R[cc][0]),
                                           __fmul_rn(tmp[a][1], R[cc][1])),
                                 __fmul_rn(tmp[a][2], R[cc][2]));

    float* oA = g_params + c * 12;
    oA[0] = centers[c * 3 + 0];
    oA[1] = centers[c * 3 + 1];
    oA[2] = centers[c * 3 + 2];
    oA[3]  = M[0][0];
    oA[4]  = M[1][0]; oA[5]  = M[2][0]; oA[6]  = M[0][1]; oA[7]  = M[1][1];
    oA[8]  = M[2][1]; oA[9]  = M[0][2]; oA[10] = M[1][2]; oA[11] = M[2][2];
}

// ---------------------------------------------------------------------------
// u32 sorting network, ascending — each CE is 2x IMNMX. All static indexing.
// ---------------------------------------------------------------------------
__device__ __forceinline__ void ce_asc(u32& a, u32& b) {
    u32 lo = min(a, b);
    u32 hi = max(a, b);
    a = lo; b = hi;
}

__device__ __forceinline__ void sort16_asc(u32 v[16]) {
#pragma unroll
    for (int p = 1; p < 16; p <<= 1) {
#pragma unroll
        for (int k = p; k >= 1; k >>= 1) {
#pragma unroll
            for (int j = k & (p - 1); j + k < 16; j += 2 * k) {
#pragma unroll
                for (int i = 0; i < k && (i + j + k) < 16; i++) {
                    if (((i + j) / (2 * p)) == ((i + j + k) / (2 * p))) {
                        ce_asc(v[i + j], v[i + j + k]);
                    }
                }
            }
        }
    }
}

// R asc, C asc -> R = 16 smallest of union; r17 = min over discarded (scalar).
template <bool CLEANUP>
__device__ __forceinline__ void merge16_asc(u32 R[16], const u32 C[16], u32& r17) {
#pragma unroll
    for (int i = 0; i < 16; i++) {
        u32 b = C[15 - i];
        u32 mx = max(R[i], b);
        R[i] = min(R[i], b);
        r17 = min(r17, mx);
    }
    if (CLEANUP) {
#pragma unroll
        for (int d = 8; d >= 1; d >>= 1) {
#pragma unroll
            for (int i = 0; i < 16; i++) {
                if ((i & d) == 0) ce_asc(R[i], R[i + d]);
            }
        }
    }
}

__device__ __forceinline__ float ex2_fast(float x) {
    float r;
    asm("ex2.approx.f32 %0, %1;" : "=f"(r) : "f"(x));
    return r;
}

// Quadratic form — bit-identical grouping to the passing R4/R6/R7/R11 kernels.
__device__ __forceinline__ float quadA(const float4* sA, int c,
                                       float x, float y, float z) {
    float4 a0 = sA[c * 3 + 0];
    float4 a1 = sA[c * 3 + 1];
    float4 a2 = sA[c * 3 + 2];
    float dx = x - a0.x, dy = y - a0.y, dz = z - a0.z;
    float t0 = fmaf(dz, a1.y, fmaf(dy, a1.x, __fmul_rn(dx, a0.w)));
    float t1 = fmaf(dz, a2.x, fmaf(dy, a1.w, __fmul_rn(dx, a1.z)));
    float t2 = fmaf(dz, a2.w, fmaf(dy, a2.z, __fmul_rn(dx, a2.y)));
    return __fadd_rn(__fadd_rn(__fmul_rn(t0, dx), __fmul_rn(t1, dy)),
                     __fmul_rn(t2, dz));
}

// ---------------------------------------------------------------------------
// Main: one thread per point. Keys = (qbits & ~0x7F) | idx. On a truncated
// 16/17 boundary tie: ONE exact rescan + tiny in-bucket selection.
// __launch_bounds__(128, 6): 85-reg cap -> 24 warps/SM (was 5 -> 88 regs,
// ~16 warps) — occupancy is the binding constraint per R11 profile.
// ---------------------------------------------------------------------------
__global__ void __launch_bounds__(TPB, 6)
main_kernel(const float* __restrict__ xyz,
            const float4* __restrict__ rgbs,
            const float* __restrict__ dists,
            const float* __restrict__ centers,
            float* __restrict__ out, int out_size) {
    __shared__ float4 sA[NC * 3];             // 6 KB
    __shared__ unsigned char slist[TPB * 16]; // 2 KB: selected indices
    __shared__ u64 sbucket[TPB * 8];          // 8 KB: boundary-bucket scratch
    __shared__ float sred[TPB];
    __shared__ bool sLast;

    int tid = threadIdx.x;
#pragma unroll
    for (int i = tid; i < NC * 3; i += TPB)
        sA[i] = reinterpret_cast<const float4*>(g_params)[i];
    __syncthreads();

    int p = blockIdx.x * TPB + tid;
    float x = xyz[3 * p + 0];
    float y = xyz[3 * p + 1];
    float z = xyz[3 * p + 2];

    u32 R[16];
    u32 r17 = 0xFFFFFFFFu;
    float pen = 0.0f;
    const float CEXP = -0.72134752044448170f;  // -0.5*log2(e)
    const float K_ADD = 2.3219280948873623f;   // log2(5)

    // ---- Pass 1: scalar q for all centers; sort (truncq|idx) keys ----
#pragma unroll 1
    for (int base = 0; base < 8; base++) {
        u32 C[16];
#pragma unroll
        for (int j = 0; j < 16; j++) {
            int c = base * 16 + j;
            float q = quadA(sA, c, x, y, z);
            float e = ex2_fast(fmaf(q, CEXP, K_ADD));
            pen += fmaxf(e - 0.01f, 0.0f);
            u32 qb = __float_as_uint(fmaxf(q, 0.0f));
            C[j] = (qb & 0xFFFFFF80u) | (u32)c;
        }
        sort16_asc(C);
        if (base == 0) {
#pragma unroll
            for (int i = 0; i < 16; i++) R[i] = C[i];
        } else if (base < 7) {
            merge16_asc<true>(R, C, r17);
        } else {
            merge16_asc<false>(R, C, r17);  // final: set only, no cleanup
        }
    }

    // boundary key (16th by (truncq,idx)) via max-tree
    u32 tq = R[0];
#pragma unroll
    for (int i = 1; i < 16; i++) tq = max(tq, R[i]);

    // Common path: selected indices straight from keys (static unroll).
    unsigned char* ml = slist + tid * 16;
#pragma unroll
    for (int i = 0; i < 16; i++) ml[i] = (unsigned char)(R[i] & 0x7Fu);

    // ---- Boundary-tie resolution: one exact rescan + in-bucket pick ----
    if (((tq ^ r17) & 0xFFFFFF80u) == 0u) {
        u32 btr = tq & 0xFFFFFF80u;
        u64* myb = sbucket + tid * 8;
        int m = 0, nb = 0;
#pragma unroll 1
        for (int c = 0; c < NC; c++) {
            float q = quadA(sA, c, x, y, z);
            u32 qb = __float_as_uint(fmaxf(q, 0.0f));
            u32 t = qb & 0xFFFFFF80u;
            if (t < btr) {               // provably in top-16
                ml[m] = (unsigned char)c;
                m++;
            } else if (t == btr && nb < 8) {
                myb[nb] = (((u64)qb << 7) | (u32)c) + 1ull;
                nb++;
            }
        }
        // pick the (16-m) smallest bucket members by exact (q, idx)
        u64 prev = 0ull;
#pragma unroll 1
        for (int r = m; r < 16; r++) {
            u64 best = ~0ull;
#pragma unroll 1
            for (int i = 0; i < nb; i++) {
                u64 k = myb[i];
                if (k > prev && k < best) best = k;
            }
            prev = best;
            ml[r] = (unsigned char)((best - 1ull) & 0x7Fu);
        }
    }

    // ---- Gather: 16 selected; exact weight from recomputed scalar q ----
    float dp = dists[p];
    const float LOG2E = 1.4426950408889634f;
    float sumw = 0.0f;
    float o0 = 0.0f, o1 = 0.0f, o2 = 0.0f, o3 = 0.0f;
#pragma unroll
    for (int i = 0; i < 16; i++) {
        int c = (int)ml[i];
        float q = quadA(sA, c, x, y, z);
        float qc = fmaxf(q, 0.0f);
        float w = __fmul_rn(5.0f, ex2_fast(__fmul_rn(qc, CEXP)));
        w = (w >= 0.01f) ? w : 0.0f;
        sumw += w;
        if (w > 0.0f) {
            float4 g = __ldg(&rgbs[(size_t)c * NP + p]);
            float alpha = 1.0f - ex2_fast(fmaxf(g.w, 0.0f) * dp * (-LOG2E));
            o0 = fmaf(w, g.x, o0);
            o1 = fmaf(w, g.y, o1);
            o2 = fmaf(w, g.z, o2);
            o3 = fmaf(w, alpha, o3);
        }
    }
    float inv = __fdiv_rn(1.0f, __fadd_rn(sumw, 1e-7f));
    reinterpret_cast<float4*>(out)[p] =
        make_float4(o0 * inv, o1 * inv, o2 * inv, o3 * inv);

    // ---- deterministic block reduction of penalty ----
    sred[tid] = pen;
    __syncthreads();
#pragma unroll
    for (int s = TPB / 2; s > 0; s >>= 1) {
        if (tid < s) sred[tid] += sred[tid + s];
        __syncthreads();
    }
    if (tid == 0) {
        g_partial[blockIdx.x] = sred[0];
        __threadfence();
        u32 old = atomicInc(&g_done, NBLK - 1);
        sLast = (old == NBLK - 1);
    }
    __syncthreads();

    // ---- Last block: finalize pen (deterministic fixed-order sum) ----
    if (sLast) {
        __shared__ double sd[TPB];
        double s = 0.0;
#pragma unroll
        for (int i = 0; i < NBLK / TPB; i++)
            s += (double)g_partial[tid * (NBLK / TPB) + i];
        sd[tid] = s;
        __syncthreads();
        if (tid == 0) {
            double tot = 0.0;
            for (int i = 0; i < TPB; i++) tot += sd[i];
            float bbox = 0.0f;
            for (int i = 0; i < NC * 3; i++) {
                float v = centers[i];
                bbox += fmaxf(v - 0.5f, 0.0f) + fmaxf(-0.5f - v, 0.0f);
            }
            float pv = (float)(0.001 * tot / (double)NP) + bbox;
            if (out_size > 4 * NP) {
                out[4 * NP] = pv;
                out[out_size - 1] = pv;
            }
        }
    }
}

// ---------------------------------------------------------------------------
extern "C" void kernel_launch(void* const* d_in, const int* in_sizes, int n_in,
                              void* d_out, int out_size) {
    const float* xyz = nullptr;
    const float* dists = nullptr;
    const float4* rgbs = nullptr;
    const float* small3[3] = {nullptr, nullptr, nullptr};
    int nsmall = 0;
    for (int i = 0; i < n_in; i++) {
        int sz = in_sizes[i];
        if (sz == NP * 3)                xyz   = (const float*)d_in[i];
        else if (sz == NC * NP * 4)      rgbs  = (const float4*)d_in[i];
        else if (sz == NP)               dists = (const float*)d_in[i];
        else if (sz == NC * 3 && nsmall < 3) small3[nsmall++] = (const float*)d_in[i];
    }
    const float* centers = small3[0];
    const float* radii   = small3[1];
    const float* rots    = small3[2];

    setup_kernel<<<NC, 8>>>(centers, radii, rots);
    main_kernel<<<NBLK, TPB>>>(xyz, rgbs, dists, centers, (float*)d_out, out_size);
}

// round 13
// speedup vs baseline: 2.4106x; 1.0187x over previous
#include <cuda_runtime.h>
#include <cstdint>

typedef unsigned long long u64;
typedef unsigned int u32;

#define NP 131072
#define NC 128
#define TPB 128
#define NBLK (NP / TPB)   // 1024

__device__ __align__(16) float g_params[NC * 12];
__device__ float g_partial[NBLK];
__device__ u32 g_done = 0;   // self-resetting via atomicInc wrap

// ---------------------------------------------------------------------------
// Setup: 128 blocks (1/center); 6 threads do the 6 fp64 trig calls in parallel.
// Numerics identical to passing R4/R6/R7/R11/R12.
// ---------------------------------------------------------------------------
__global__ void setup_kernel(const float* __restrict__ centers,
                             const float* __restrict__ radii,
                             const float* __restrict__ rot) {
    __shared__ float strig[6];
    int t = threadIdx.x;
    int c = blockIdx.x;
    if (t < 6) {
        int axis = t >> 1;
        double a = (double)rot[c * 3 + axis];
        strig[t] = (t & 1) ? (float)sin(a) : (float)cos(a);
    }
    __syncthreads();
    if (t != 0) return;

    float d[3];
#pragma unroll
    for (int i = 0; i < 3; i++)
        d[i] = __fdiv_rn(1.0f, __fadd_rn(fabsf(radii[c * 3 + i]), 1e-8f));

    float cx = strig[0], sx = strig[1];
    float cy = strig[2], sy = strig[3];
    float cz = strig[4], sz = strig[5];

    float R[3][3];
    R[0][0] = __fmul_rn(cz, cy);
    R[0][1] = __fsub_rn(__fmul_rn(__fmul_rn(cz, sy), sx), __fmul_rn(sz, cx));
    R[0][2] = __fadd_rn(__fmul_rn(__fmul_rn(cz, sy), cx), __fmul_rn(sz, sx));
    R[1][0] = __fmul_rn(sz, cy);
    R[1][1] = __fadd_rn(__fmul_rn(__fmul_rn(sz, sy), sx), __fmul_rn(cz, cx));
    R[1][2] = __fsub_rn(__fmul_rn(__fmul_rn(sz, sy), cx), __fmul_rn(cz, sx));
    R[2][0] = -sy;
    R[2][1] = __fmul_rn(cy, sx);
    R[2][2] = __fmul_rn(cy, cx);

    float tmp[3][3];
#pragma unroll
    for (int a = 0; a < 3; a++)
#pragma unroll
        for (int b = 0; b < 3; b++)
            tmp[a][b] = __fmul_rn(R[a][b], d[b]);

    float M[3][3];
#pragma unroll
    for (int a = 0; a < 3; a++)
#pragma unroll
        for (int cc = 0; cc < 3; cc++)
            M[a][cc] = __fadd_rn(__fadd_rn(__fmul_rn(tmp[a][0], R[cc][0]),
                                           __fmul_rn(tmp[a][1], R[cc][1])),
                                 __fmul_rn(tmp[a][2], R[cc][2]));

    float* oA = g_params + c * 12;
    oA[0] = centers[c * 3 + 0];
    oA[1] = centers[c * 3 + 1];
    oA[2] = centers[c * 3 + 2];
    oA[3]  = M[0][0];
    oA[4]  = M[1][0]; oA[5]  = M[2][0]; oA[6]  = M[0][1]; oA[7]  = M[1][1];
    oA[8]  = M[2][1]; oA[9]  = M[0][2]; oA[10] = M[1][2]; oA[11] = M[2][2];
}

// ---------------------------------------------------------------------------
// u32 sorting network, ascending — each CE is 2x IMNMX. All static indexing.
// ---------------------------------------------------------------------------
__device__ __forceinline__ void ce_asc(u32& a, u32& b) {
    u32 lo = min(a, b);
    u32 hi = max(a, b);
    a = lo; b = hi;
}

__device__ __forceinline__ void sort16_asc(u32 v[16]) {
#pragma unroll
    for (int p = 1; p < 16; p <<= 1) {
#pragma unroll
        for (int k = p; k >= 1; k >>= 1) {
#pragma unroll
            for (int j = k & (p - 1); j + k < 16; j += 2 * k) {
#pragma unroll
                for (int i = 0; i < k && (i + j + k) < 16; i++) {
                    if (((i + j) / (2 * p)) == ((i + j + k) / (2 * p))) {
                        ce_asc(v[i + j], v[i + j + k]);
                    }
                }
            }
        }
    }
}

// R asc, C asc -> R = 16 smallest of union; r17 = min over discarded (scalar).
template <bool CLEANUP>
__device__ __forceinline__ void merge16_asc(u32 R[16], const u32 C[16], u32& r17) {
#pragma unroll
    for (int i = 0; i < 16; i++) {
        u32 b = C[15 - i];
        u32 mx = max(R[i], b);
        R[i] = min(R[i], b);
        r17 = min(r17, mx);
    }
    if (CLEANUP) {
#pragma unroll
        for (int d = 8; d >= 1; d >>= 1) {
#pragma unroll
            for (int i = 0; i < 16; i++) {
                if ((i & d) == 0) ce_asc(R[i], R[i + d]);
            }
        }
    }
}

__device__ __forceinline__ float ex2_fast(float x) {
    float r;
    asm("ex2.approx.f32 %0, %1;" : "=f"(r) : "f"(x));
    return r;
}

// Quadratic form — bit-identical grouping to the passing R4/R6/R7/R11/R12.
__device__ __forceinline__ float quadA(const float4* sA, int c,
                                       float x, float y, float z) {
    float4 a0 = sA[c * 3 + 0];
    float4 a1 = sA[c * 3 + 1];
    float4 a2 = sA[c * 3 + 2];
    float dx = x - a0.x, dy = y - a0.y, dz = z - a0.z;
    float t0 = fmaf(dz, a1.y, fmaf(dy, a1.x, __fmul_rn(dx, a0.w)));
    float t1 = fmaf(dz, a2.x, fmaf(dy, a1.w, __fmul_rn(dx, a1.z)));
    float t2 = fmaf(dz, a2.w, fmaf(dy, a2.z, __fmul_rn(dx, a2.y)));
    return __fadd_rn(__fadd_rn(__fmul_rn(t0, dx), __fmul_rn(t1, dy)),
                     __fmul_rn(t2, dz));
}

// ---------------------------------------------------------------------------
// Main: one thread per point. Keys = (qbits & ~0x7F) | idx; boundary-tie
// resolution via one exact rescan. Gather is done in ASCENDING INDEX order
// (16-byte sort) so warp lanes hit nearly the same rgbs rows -> coalesced.
// ---------------------------------------------------------------------------
__global__ void __launch_bounds__(TPB, 7)
main_kernel(const float* __restrict__ xyz,
            const float4* __restrict__ rgbs,
            const float* __restrict__ dists,
            const float* __restrict__ centers,
            float* __restrict__ out, int out_size) {
    __shared__ float4 sA[NC * 3];                           // 6 KB
    __shared__ __align__(16) unsigned char slist[TPB * 16]; // 2 KB
    __shared__ u64 sbucket[TPB * 8];                        // 8 KB
    __shared__ float sred[TPB];
    __shared__ bool sLast;

    int tid = threadIdx.x;
#pragma unroll
    for (int i = tid; i < NC * 3; i += TPB)
        sA[i] = reinterpret_cast<const float4*>(g_params)[i];
    __syncthreads();

    int p = blockIdx.x * TPB + tid;
    float x = xyz[3 * p + 0];
    float y = xyz[3 * p + 1];
    float z = xyz[3 * p + 2];

    u32 R[16];
    u32 r17 = 0xFFFFFFFFu;
    float pen = 0.0f;
    const float CEXP = -0.72134752044448170f;  // -0.5*log2(e)
    const float K_ADD = 2.3219280948873623f;   // log2(5)

    // ---- Pass 1: scalar q for all centers; sort (truncq|idx) keys ----
#pragma unroll 1
    for (int base = 0; base < 8; base++) {
        u32 C[16];
#pragma unroll
        for (int j = 0; j < 16; j++) {
            int c = base * 16 + j;
            float q = quadA(sA, c, x, y, z);
            float e = ex2_fast(fmaf(q, CEXP, K_ADD));
            pen += fmaxf(e - 0.01f, 0.0f);
            u32 qb = __float_as_uint(fmaxf(q, 0.0f));
            C[j] = (qb & 0xFFFFFF80u) | (u32)c;
        }
        sort16_asc(C);
        if (base == 0) {
#pragma unroll
            for (int i = 0; i < 16; i++) R[i] = C[i];
        } else if (base < 7) {
            merge16_asc<true>(R, C, r17);
        } else {
            merge16_asc<false>(R, C, r17);  // final: set only, no cleanup
        }
    }

    // boundary key (16th by (truncq,idx)) via max-tree
    u32 tq = R[0];
#pragma unroll
    for (int i = 1; i < 16; i++) tq = max(tq, R[i]);

    // Common path: selected indices straight from keys (static unroll).
    unsigned char* ml = slist + tid * 16;
#pragma unroll
    for (int i = 0; i < 16; i++) ml[i] = (unsigned char)(R[i] & 0x7Fu);

    // ---- Boundary-tie resolution: one exact rescan + in-bucket pick ----
    if (((tq ^ r17) & 0xFFFFFF80u) == 0u) {
        u32 btr = tq & 0xFFFFFF80u;
        u64* myb = sbucket + tid * 8;
        int m = 0, nb = 0;
#pragma unroll 1
        for (int c = 0; c < NC; c++) {
            float q = quadA(sA, c, x, y, z);
            u32 qb = __float_as_uint(fmaxf(q, 0.0f));
            u32 t = qb & 0xFFFFFF80u;
            if (t < btr) {               // provably in top-16
                ml[m] = (unsigned char)c;
                m++;
            } else if (t == btr && nb < 8) {
                myb[nb] = (((u64)qb << 7) | (u32)c) + 1ull;
                nb++;
            }
        }
        // pick the (16-m) smallest bucket members by exact (q, idx)
        u64 prev = 0ull;
#pragma unroll 1
        for (int r = m; r < 16; r++) {
            u64 best = ~0ull;
#pragma unroll 1
            for (int i = 0; i < nb; i++) {
                u64 k = myb[i];
                if (k > prev && k < best) best = k;
            }
            prev = best;
            ml[r] = (unsigned char)((best - 1ull) & 0x7Fu);
        }
    }

    // ---- Re-sort the 16 selected indices ASCENDING (index order) so the
    //      gather below is warp-coalesced on rgbs rows. One uint4 LDS +
    //      byte extraction + sort16 (126 IMNMX).
    u32 v[16];
    {
        uint4 packed = *reinterpret_cast<const uint4*>(ml);
        u32 w0 = packed.x, w1 = packed.y, w2 = packed.z, w3 = packed.w;
        v[0]  = w0 & 0xFFu; v[1]  = (w0 >> 8) & 0xFFu;
        v[2]  = (w0 >> 16) & 0xFFu; v[3]  = w0 >> 24;
        v[4]  = w1 & 0xFFu; v[5]  = (w1 >> 8) & 0xFFu;
        v[6]  = (w1 >> 16) & 0xFFu; v[7]  = w1 >> 24;
        v[8]  = w2 & 0xFFu; v[9]  = (w2 >> 8) & 0xFFu;
        v[10] = (w2 >> 16) & 0xFFu; v[11] = w2 >> 24;
        v[12] = w3 & 0xFFu; v[13] = (w3 >> 8) & 0xFFu;
        v[14] = (w3 >> 16) & 0xFFu; v[15] = w3 >> 24;
        sort16_asc(v);
    }

    // ---- Gather (index-ascending): exact weight from recomputed scalar q ----
    float dp = dists[p];
    const float LOG2E = 1.4426950408889634f;
    float sumw = 0.0f;
    float o0 = 0.0f, o1 = 0.0f, o2 = 0.0f, o3 = 0.0f;
#pragma unroll
    for (int i = 0; i < 16; i++) {
        int c = (int)v[i];
        float q = quadA(sA, c, x, y, z);
        float qc = fmaxf(q, 0.0f);
        float w = __fmul_rn(5.0f, ex2_fast(__fmul_rn(qc, CEXP)));
        w = (w >= 0.01f) ? w : 0.0f;
        sumw += w;
        if (w > 0.0f) {
            float4 g = __ldg(&rgbs[(size_t)c * NP + p]);
            float alpha = 1.0f - ex2_fast(fmaxf(g.w, 0.0f) * dp * (-LOG2E));
            o0 = fmaf(w, g.x, o0);
            o1 = fmaf(w, g.y, o1);
            o2 = fmaf(w, g.z, o2);
            o3 = fmaf(w, alpha, o3);
        }
    }
    float inv = __fdiv_rn(1.0f, __fadd_rn(sumw, 1e-7f));
    reinterpret_cast<float4*>(out)[p] =
        make_float4(o0 * inv, o1 * inv, o2 * inv, o3 * inv);

    // ---- deterministic block reduction of penalty ----
    sred[tid] = pen;
    __syncthreads();
#pragma unroll
    for (int s = TPB / 2; s > 0; s >>= 1) {
        if (tid < s) sred[tid] += sred[tid + s];
        __syncthreads();
    }
    if (tid == 0) {
        g_partial[blockIdx.x] = sred[0];
        __threadfence();
        u32 old = atomicInc(&g_done, NBLK - 1);
        sLast = (old == NBLK - 1);
    }
    __syncthreads();

    // ---- Last block: finalize pen (deterministic fixed-order sum) ----
    if (sLast) {
        __shared__ double sd[TPB];
        double s = 0.0;
#pragma unroll
        for (int i = 0; i < NBLK / TPB; i++)
            s += (double)g_partial[tid * (NBLK / TPB) + i];
        sd[tid] = s;
        __syncthreads();
        if (tid == 0) {
            double tot = 0.0;
            for (int i = 0; i < TPB; i++) tot += sd[i];
            float bbox = 0.0f;
            for (int i = 0; i < NC * 3; i++) {
                float val = centers[i];
                bbox += fmaxf(val - 0.5f, 0.0f) + fmaxf(-0.5f - val, 0.0f);
            }
            float pv = (float)(0.001 * tot / (double)NP) + bbox;
            if (out_size > 4 * NP) {
                out[4 * NP] = pv;
                out[out_size - 1] = pv;
            }
        }
    }
}

// ---------------------------------------------------------------------------
extern "C" void kernel_launch(void* const* d_in, const int* in_sizes, int n_in,
                              void* d_out, int out_size) {
    const float* xyz = nullptr;
    const float* dists = nullptr;
    const float4* rgbs = nullptr;
    const float* small3[3] = {nullptr, nullptr, nullptr};
    int nsmall = 0;
    for (int i = 0; i < n_in; i++) {
        int sz = in_sizes[i];
        if (sz == NP * 3)                xyz   = (const float*)d_in[i];
        else if (sz == NC * NP * 4)      rgbs  = (const float4*)d_in[i];
        else if (sz == NP)               dists = (const float*)d_in[i];
        else if (sz == NC * 3 && nsmall < 3) small3[nsmall++] = (const float*)d_in[i];
    }
    const float* centers = small3[0];
    const float* radii   = small3[1];
    const float* rots    = small3[2];

    setup_kernel<<<NC, 8>>>(centers, radii, rots);
    main_kernel<<<NBLK, TPB>>>(xyz, rgbs, dists, centers, (float*)d_out, out_size);
}